// round 14
// baseline (speedup 1.0000x reference)
#include <cuda_runtime.h>
#include <cuda_bf16.h>
#include <math.h>
#include <stdint.h>

// Problem constants
#define BB 4096
#define DD 256
#define HH 512
#define TT 45
#define N4H 2048

// step-GEMM tile config: 512 threads, warp grid 4x4, warp tile 32x32
#define BM 128
#define BN 128
#define BK 32
#define LDA_H 40     // As row stride halfs (80B) - conflict-free ldmatrix
#define LDB_H 136    // Bs row stride halfs (272B) - conflict-free
#define NSTG 3
#define STG_A (BM * LDA_H * 2)          // 10240 B
#define STG_BB (BK * LDB_H * 2)         // 8704 B
#define STG_SZ (STG_A + STG_BB)         // 18944 B
#define CS_LD 36                        // c-tile row stride (f32; 144B)
#define CS_OFF (NSTG * STG_SZ)          // 56832
#define CS_BYTES (BM * CS_LD * 4)       // 18432
#define DYN_SMEM (CS_OFF + CS_BYTES)    // 75264  -> 2 CTAs/SM

// ---------------- scratch ----------------
__device__ float g_C01[BB * 2 * HH];            // [B][1024]: c0 | c1
__device__ float g_intent[BB];
__device__ float g_bsum0p[N4H];
__device__ float g_bsum1p[N4H];
__device__ float g_wrowp [N4H];
__device__ float g_Wo1t[32 * HH];               // Wo1 transposed [32][512]
__device__ float g_Wg1t[32 * HH];               // Wg1 transposed [32][512]

__device__ __nv_bfloat16 g_Xcb [BB * N4H];      // bf16 Xc
__device__ __nv_bfloat16 g_bH01[BB * 2 * HH];   // [B][1024]: h0 | h1
__device__ __nv_bfloat16 g_bEnc [BB * DD];
__device__ __nv_bfloat16 g_bCtx [BB * DD];
__device__ __nv_bfloat16 g_bWh  [DD * 2 * HH];
__device__ __nv_bfloat16 g_bWc  [DD * 2 * HH];
__device__ __nv_bfloat16 g_bWi0c[DD * N4H];     // [256][2048] perm
__device__ __nv_bfloat16 g_bWhh0[HH * N4H];     // [512][2048] perm
__device__ __nv_bfloat16 g_bW1s [2 * HH * N4H]; // [1024][2048]: Wih1|Whh1 perm

// ---------------- low-level helpers ----------------
__device__ __forceinline__ uint32_t smem_u32(const void* p) {
    uint32_t a;
    asm("{ .reg .u64 t; cvta.to.shared.u64 t, %1; cvt.u32.u64 %0, t; }"
        : "=r"(a) : "l"(p));
    return a;
}
__device__ __forceinline__ void cp16(uint32_t dst_sh, const void* src) {
    asm volatile("cp.async.cg.shared.global [%0], [%1], 16;\n"
                 :: "r"(dst_sh), "l"(src));
}
#define CP_COMMIT() asm volatile("cp.async.commit_group;\n" ::: "memory")
template <int N>
__device__ __forceinline__ void cp_wait() {
    asm volatile("cp.async.wait_group %0;\n" :: "n"(N) : "memory");
}
__device__ __forceinline__ void ldm_x4(uint32_t r[4], uint32_t addr) {
    asm volatile("ldmatrix.sync.aligned.m8n8.x4.shared.b16 {%0,%1,%2,%3}, [%4];\n"
                 : "=r"(r[0]), "=r"(r[1]), "=r"(r[2]), "=r"(r[3]) : "r"(addr));
}
__device__ __forceinline__ void ldm_x4t(uint32_t r[4], uint32_t addr) {
    asm volatile("ldmatrix.sync.aligned.m8n8.x4.trans.shared.b16 {%0,%1,%2,%3}, [%4];\n"
                 : "=r"(r[0]), "=r"(r[1]), "=r"(r[2]), "=r"(r[3]) : "r"(addr));
}
__device__ __forceinline__ void mma_bf16(float c[4], const uint32_t a[4],
                                         uint32_t b0, uint32_t b1) {
    asm volatile(
        "mma.sync.aligned.m16n8k16.row.col.f32.bf16.bf16.f32 "
        "{%0,%1,%2,%3}, {%4,%5,%6,%7}, {%8,%9}, {%0,%1,%2,%3};\n"
        : "+f"(c[0]), "+f"(c[1]), "+f"(c[2]), "+f"(c[3])
        : "r"(a[0]), "r"(a[1]), "r"(a[2]), "r"(a[3]), "r"(b0), "r"(b1));
}
__device__ __forceinline__ float tanh_fast(float x) {
    float y; asm("tanh.approx.f32 %0, %1;" : "=f"(y) : "f"(x)); return y;
}
__device__ __forceinline__ float sig_fast(float x) {
    return fmaf(tanh_fast(0.5f * x), 0.5f, 0.5f);
}

// ===========================================================================
// Step GEMM (512 threads, 3-stage pipeline, 1 sync/K-tile, c-tile prefetch):
// V[m,n] = sum_k A[m,k]*B[k,n] + bias[n] (+ Xaddb[m,n] + intent[m]*wrow[n])
// cell_c==null: plain: V -> Xout (bf16, ld xo_ld).
// cell_c!=null: gate-interleaved fused LSTM cell (SMEM-staged; c prefetched
//   via cp.async at kernel start). Xaddb read from global in epilogue.
// ===========================================================================
__global__ __launch_bounds__(512, 2)
void gemm_step(const __nv_bfloat16* __restrict__ A, int lda,
               const __nv_bfloat16* __restrict__ B, int ldb, int K,
               const float* __restrict__ bias,
               const __nv_bfloat16* __restrict__ Xaddb,
               const float* __restrict__ intent,
               const float* __restrict__ wrow,
               __nv_bfloat16* __restrict__ Xout, int xo_ld,
               float* __restrict__ cell_c, int cc_ld, int cc_off,
               __nv_bfloat16* __restrict__ Hb, int hb_ld, int hb_off)
{
    extern __shared__ __align__(16) char smraw[];

    const int tid  = threadIdx.x;
    const int lane = tid & 31;
    const int wid  = tid >> 5;              // 0..15
    const int wm   = (wid & 3) * 32;
    const int wn   = (wid >> 2) * 32;
    const int g    = lane >> 2;
    const int t    = lane & 3;
    const int m0   = blockIdx.y * BM;
    const int n0   = blockIdx.x * BN;
    const int hid0 = n0 >> 2;

    const uint32_t smb = smem_u32(smraw);

    // c-tile prefetch (own commit group, FIRST) -- rides under the mainloop
    if (cell_c) {
        #pragma unroll
        for (int k2 = 0; k2 < 2; ++k2) {
            int idx = tid + k2 * 512;       // 1024 segs = 128 rows x 8
            int r = idx >> 3, s = idx & 7;
            cp16(smb + CS_OFF + r * (CS_LD * 4) + s * 16,
                 cell_c + (size_t)(m0 + r) * cc_ld + cc_off + hid0 + s * 4);
        }
        CP_COMMIT();
    }

    float acc[2][4][4];
    #pragma unroll
    for (int mi = 0; mi < 2; ++mi)
        #pragma unroll
        for (int ni = 0; ni < 4; ++ni)
            #pragma unroll
            for (int r = 0; r < 4; ++r) acc[mi][ni][r] = 0.f;

    // loaders (one cp16 each for A and B)
    const int arow = tid >> 2;              // 0..127
    const int acol = (tid & 3) * 8;         // halfs
    const int brow = tid >> 4;              // 0..31
    const int bcol = (tid & 15) * 8;        // halfs
    const int ktotal = K / BK;

    auto issue = [&](int kt) {
        const uint32_t base = smb + (kt % NSTG) * STG_SZ;
        cp16(base + (arow * LDA_H + acol) * 2,
             A + (size_t)(m0 + arow) * lda + kt * BK + acol);
        cp16(base + STG_A + (brow * LDB_H + bcol) * 2,
             B + (size_t)(kt * BK + brow) * ldb + n0 + bcol);
        CP_COMMIT();
    };

    issue(0);
    if (ktotal > 1) issue(1);

    const int a_lrow = lane & 15;
    const int a_lcol = (lane >> 4) << 3;
    const int b_lrow = (lane & 7) + (lane & 8);
    const int b_lcol = (lane >> 4) << 3;

    #pragma unroll 1
    for (int kt = 0; kt < ktotal; ++kt) {
        if (kt + 1 < ktotal) cp_wait<1>(); else cp_wait<0>();
        __syncthreads();
        if (kt + 2 < ktotal) issue(kt + 2);

        const uint32_t sb = smb + (kt % NSTG) * STG_SZ;
        const uint32_t asb = sb;
        const uint32_t bsb = sb + STG_A;

        #pragma unroll
        for (int kk = 0; kk < 2; ++kk) {
            const int kc = kk * 16;
            uint32_t afr[2][4];
            #pragma unroll
            for (int mi = 0; mi < 2; ++mi)
                ldm_x4(afr[mi], asb + ((wm + mi * 16 + a_lrow) * LDA_H + kc + a_lcol) * 2);
            uint32_t bfr[4][2];
            #pragma unroll
            for (int nj = 0; nj < 2; ++nj) {
                uint32_t r[4];
                ldm_x4t(r, bsb + ((kc + b_lrow) * LDB_H + wn + nj * 16 + b_lcol) * 2);
                bfr[nj*2+0][0] = r[0]; bfr[nj*2+0][1] = r[1];
                bfr[nj*2+1][0] = r[2]; bfr[nj*2+1][1] = r[3];
            }
            #pragma unroll
            for (int mi = 0; mi < 2; ++mi)
                #pragma unroll
                for (int ni = 0; ni < 4; ++ni)
                    mma_bf16(acc[mi][ni], afr[mi], bfr[ni][0], bfr[ni][1]);
        }
    }

    // ---------------- epilogue ----------------
    if (cell_c == nullptr) {
        // plain path: bias + bf16 store (used for Xc precompute)
        #pragma unroll
        for (int mi = 0; mi < 2; ++mi) {
            const int row0 = m0 + wm + mi * 16 + g;
            const int row1 = row0 + 8;
            #pragma unroll
            for (int ni = 0; ni < 4; ++ni) {
                const int col = n0 + wn + ni * 8 + t * 2;
                float b0 = bias ? bias[col] : 0.f;
                float b1 = bias ? bias[col + 1] : 0.f;
                float v00 = acc[mi][ni][0] + b0;
                float v01 = acc[mi][ni][1] + b1;
                float v10 = acc[mi][ni][2] + b0;
                float v11 = acc[mi][ni][3] + b1;
                *(__nv_bfloat162*)(Xout + (size_t)row0 * xo_ld + col) =
                    __nv_bfloat162(__float2bfloat16(v00), __float2bfloat16(v01));
                *(__nv_bfloat162*)(Xout + (size_t)row1 * xo_ld + col) =
                    __nv_bfloat162(__float2bfloat16(v10), __float2bfloat16(v11));
            }
        }
        return;
    }

    // fused cell path: c tile already in smem (prefetched); hs overlays stages
    __syncthreads();   // all warps done with stage-region ldmatrix reads
    float* cs = (float*)(smraw + CS_OFF);                   // [128][36] f32
    __nv_bfloat16* hs = (__nv_bfloat16*)smraw;              // [128][36] bf16

    const bool evenT = ((t & 1) == 0);
    const bool useX = (Xaddb != nullptr);
    #pragma unroll
    for (int mi = 0; mi < 2; ++mi) {
        const int r0 = wm + mi * 16 + g;
        const int r1 = r0 + 8;
        const float it0 = intent ? intent[m0 + r0] : 0.f;
        const float it1 = intent ? intent[m0 + r1] : 0.f;
        #pragma unroll
        for (int ni = 0; ni < 4; ++ni) {
            const int lcol = wn + ni * 8 + t * 2;
            const int col  = n0 + lcol;
            const int hidl = lcol >> 2;
            float b0 = bias ? bias[col] : 0.f;
            float b1 = bias ? bias[col + 1] : 0.f;
            float v00 = acc[mi][ni][0] + b0;
            float v01 = acc[mi][ni][1] + b1;
            float v10 = acc[mi][ni][2] + b0;
            float v11 = acc[mi][ni][3] + b1;
            if (intent) {
                float w0 = wrow[col], w1 = wrow[col + 1];
                v00 = fmaf(it0, w0, v00); v01 = fmaf(it0, w1, v01);
                v10 = fmaf(it1, w0, v10); v11 = fmaf(it1, w1, v11);
            }
            if (useX) {
                float2 x0 = __bfloat1622float2(
                    *(const __nv_bfloat162*)(Xaddb + (size_t)(m0 + r0) * N4H + col));
                float2 x1 = __bfloat1622float2(
                    *(const __nv_bfloat162*)(Xaddb + (size_t)(m0 + r1) * N4H + col));
                v00 += x0.x; v01 += x0.y; v10 += x1.x; v11 += x1.y;
            }

            // even t: (i,f); odd t: (g,o)
            float a0, a1;
            if (evenT) { a0 = sig_fast(v00);  a1 = sig_fast(v10); }
            else       { a0 = tanh_fast(v00); a1 = tanh_fast(v10); }
            float bv0 = sig_fast(v01);
            float bv1 = sig_fast(v11);

            float pa0 = __shfl_xor_sync(0xffffffffu, a0, 1);
            float pa1 = __shfl_xor_sync(0xffffffffu, a1, 1);

            float tc0 = 0.f, tc1 = 0.f;
            if (evenT) {
                float cn0 = fmaf(bv0, cs[r0 * CS_LD + hidl], a0 * pa0);
                float cn1 = fmaf(bv1, cs[r1 * CS_LD + hidl], a1 * pa1);
                cs[r0 * CS_LD + hidl] = cn0;
                cs[r1 * CS_LD + hidl] = cn1;
                tc0 = tanh_fast(cn0);
                tc1 = tanh_fast(cn1);
            }
            float q0 = __shfl_xor_sync(0xffffffffu, tc0, 1);
            float q1 = __shfl_xor_sync(0xffffffffu, tc1, 1);
            if (!evenT) {
                hs[r0 * CS_LD + hidl] = __float2bfloat16(bv0 * q0);
                hs[r1 * CS_LD + hidl] = __float2bfloat16(bv1 * q1);
            }
        }
    }
    __syncthreads();

    // coalesced store of c and h tiles
    #pragma unroll 2
    for (int i = tid; i < BM * 32; i += 512) {
        int r = i >> 5, cc = i & 31;
        cell_c[(size_t)(m0 + r) * cc_ld + cc_off + hid0 + cc] = cs[r * CS_LD + cc];
        Hb[(size_t)(m0 + r) * hb_ld + hb_off + hid0 + cc]     = hs[r * CS_LD + cc];
    }
}

// ===========================================================================
// init GEMM (256 threads, plain epilogue): C = A@B + bias
// ===========================================================================
#define IBM 128
#define IBN 128
#define IBK 32

__global__ __launch_bounds__(256, 2)
void gemm_init(const __nv_bfloat16* __restrict__ A, int lda,
               const __nv_bfloat16* __restrict__ B, int ldb, int K,
               const float* __restrict__ bias,
               float* __restrict__ C,
               __nv_bfloat16* __restrict__ Cb, int ldc)
{
    __shared__ __nv_bfloat16 As[2][IBM * LDA_H];
    __shared__ __nv_bfloat16 Bs[2][IBK * LDB_H];

    const int tid  = threadIdx.x;
    const int lane = tid & 31;
    const int wid  = tid >> 5;
    const int wm   = (wid & 1) * 64;
    const int wn   = (wid >> 1) * 32;
    const int g    = lane >> 2;
    const int t    = lane & 3;
    const int m0   = blockIdx.y * IBM;
    const int n0   = blockIdx.x * IBN;

    const uint32_t as_base = smem_u32(&As[0][0]);
    const uint32_t bs_base = smem_u32(&Bs[0][0]);
    const uint32_t as_sz = IBM * LDA_H * 2;
    const uint32_t bs_sz = IBK * LDB_H * 2;

    float acc[4][4][4];
    #pragma unroll
    for (int mi = 0; mi < 4; ++mi)
        #pragma unroll
        for (int ni = 0; ni < 4; ++ni)
            #pragma unroll
            for (int r = 0; r < 4; ++r) acc[mi][ni][r] = 0.f;

    const int arow = tid >> 1;
    const int aoff = (tid & 1) * 16;
    const int brow = tid >> 4;
    const int boff = (tid & 15) * 8;
    const int ktotal = K / IBK;

    auto issue = [&](int kt, int b) {
        const __nv_bfloat16* asrc = A + (size_t)(m0 + arow) * lda + kt * IBK + aoff;
        uint32_t adst = as_base + b * as_sz + (arow * LDA_H + aoff) * 2;
        cp16(adst, asrc);
        cp16(adst + 16, asrc + 8);
        const __nv_bfloat16* bsrc = B + (size_t)(kt * IBK + brow) * ldb + n0 + boff;
        uint32_t bdst = bs_base + b * bs_sz + (brow * LDB_H + boff) * 2;
        cp16(bdst, bsrc);
        cp16(bdst + 16 * LDB_H * 2, bsrc + (size_t)16 * ldb);
    };

    issue(0, 0);
    CP_COMMIT();

    const int a_lrow = lane & 15;
    const int a_lcol = (lane >> 4) << 3;
    const int b_lrow = (lane & 7) + (lane & 8);
    const int b_lcol = (lane >> 4) << 3;

    #pragma unroll 1
    for (int kt = 0; kt < ktotal; ++kt) {
        if (kt + 1 < ktotal) {
            issue(kt + 1, (kt + 1) & 1);
            CP_COMMIT();
            cp_wait<1>();
        } else {
            cp_wait<0>();
        }
        __syncthreads();

        const int b = kt & 1;
        const uint32_t asb = as_base + b * as_sz;
        const uint32_t bsb = bs_base + b * bs_sz;

        #pragma unroll
        for (int kk = 0; kk < 2; ++kk) {
            const int kc = kk * 16;
            uint32_t afr[4][4];
            #pragma unroll
            for (int mi = 0; mi < 4; ++mi)
                ldm_x4(afr[mi], asb + ((wm + mi * 16 + a_lrow) * LDA_H + kc + a_lcol) * 2);
            uint32_t bfr[4][2];
            #pragma unroll
            for (int nj = 0; nj < 2; ++nj) {
                uint32_t r[4];
                ldm_x4t(r, bsb + ((kc + b_lrow) * LDB_H + wn + nj * 16 + b_lcol) * 2);
                bfr[nj*2+0][0] = r[0]; bfr[nj*2+0][1] = r[1];
                bfr[nj*2+1][0] = r[2]; bfr[nj*2+1][1] = r[3];
            }
            #pragma unroll
            for (int mi = 0; mi < 4; ++mi)
                #pragma unroll
                for (int ni = 0; ni < 4; ++ni)
                    mma_bf16(acc[mi][ni], afr[mi], bfr[ni][0], bfr[ni][1]);
        }
        __syncthreads();
    }

    #pragma unroll
    for (int mi = 0; mi < 4; ++mi) {
        const int row0 = m0 + wm + mi * 16 + g;
        const int row1 = row0 + 8;
        #pragma unroll
        for (int ni = 0; ni < 4; ++ni) {
            const int col = n0 + wn + ni * 8 + t * 2;
            float b0 = bias ? bias[col] : 0.f;
            float b1 = bias ? bias[col + 1] : 0.f;
            float v00 = acc[mi][ni][0] + b0;
            float v01 = acc[mi][ni][1] + b1;
            float v10 = acc[mi][ni][2] + b0;
            float v11 = acc[mi][ni][3] + b1;
            if (C) {
                *(float2*)(C + (size_t)row0 * ldc + col) = make_float2(v00, v01);
                *(float2*)(C + (size_t)row1 * ldc + col) = make_float2(v10, v11);
            }
            if (Cb) {
                *(__nv_bfloat162*)(Cb + (size_t)row0 * ldc + col) =
                    __nv_bfloat162(__float2bfloat16(v00), __float2bfloat16(v01));
                *(__nv_bfloat162*)(Cb + (size_t)row1 * ldc + col) =
                    __nv_bfloat162(__float2bfloat16(v10), __float2bfloat16(v11));
            }
        }
    }
}

// ===========================================================================
// setup kernels
// ===========================================================================
__global__ void cvt_all_kernel(const float* __restrict__ enc,
                               const float* __restrict__ ctx,
                               const float* __restrict__ Wh,
                               const float* __restrict__ Wc,
                               __nv_bfloat16* __restrict__ bEnc,
                               __nv_bfloat16* __restrict__ bCtx,
                               __nv_bfloat16* __restrict__ bWh,
                               __nv_bfloat16* __restrict__ bWc)
{
    const int n1 = BB * DD, n2 = DD * 2 * HH;
    int i = blockIdx.x * blockDim.x + threadIdx.x;
    int stride = gridDim.x * blockDim.x;
    int total = 2 * n1 + 2 * n2;
    for (; i < total; i += stride) {
        if (i < n1)               bEnc[i]              = __float2bfloat16(enc[i]);
        else if (i < 2 * n1)      bCtx[i - n1]         = __float2bfloat16(ctx[i - n1]);
        else if (i < 2 * n1 + n2) bWh[i - 2 * n1]      = __float2bfloat16(Wh[i - 2 * n1]);
        else                      bWc[i - 2 * n1 - n2] = __float2bfloat16(Wc[i - 2 * n1 - n2]);
    }
}

// gate-interleave permutation of K x 2048 weight matrices into bf16
__global__ void cvt_perm_kernel(const float* __restrict__ Whh0,
                                const float* __restrict__ Wih1,
                                const float* __restrict__ Whh1,
                                const float* __restrict__ Wih0,
                                __nv_bfloat16* __restrict__ bWhh0,
                                __nv_bfloat16* __restrict__ bW1s,
                                __nv_bfloat16* __restrict__ bWi0c)
{
    int i = blockIdx.x * blockDim.x + threadIdx.x;
    int stride = gridDim.x * blockDim.x;
    const int nA = HH * N4H;
    const int nB = HH * N4H;
    const int nC = HH * N4H;
    const int nD = DD * N4H;
    int total = nA + nB + nC + nD;
    for (; i < total; i += stride) {
        int j = i, k, c;
        const float* src;
        __nv_bfloat16* dst;
        if (j < nA)            { src = Whh0;  dst = bWhh0; }
        else if (j < nA + nB)  { j -= nA;  src = Wih1; dst = bW1s; }
        else if (j < nA+nB+nC) { j -= nA + nB; src = Whh1; dst = bW1s + (size_t)HH * N4H; }
        else                   { j -= nA + nB + nC; src = Wih0 + N4H; dst = bWi0c; }
        k = j >> 11;
        c = j & (N4H - 1);
        int o = ((c & 3) << 9) + (c >> 2);
        dst[j] = __float2bfloat16(src[(size_t)k * N4H + o]);
    }
}

// biases (gate-permuted) + head weight transposes (Wo1,Wg1 -> [32][512])
__global__ void misc_prep_kernel(const float* __restrict__ b_ih0,
                                 const float* __restrict__ b_hh0,
                                 const float* __restrict__ b_ih1,
                                 const float* __restrict__ b_hh1,
                                 const float* __restrict__ wih0_row0,
                                 const float* __restrict__ Wo1,
                                 const float* __restrict__ Wg1,
                                 float* __restrict__ bsum0p,
                                 float* __restrict__ bsum1p,
                                 float* __restrict__ wrowp,
                                 float* __restrict__ Wo1t,
                                 float* __restrict__ Wg1t)
{
    int i = blockIdx.x * blockDim.x + threadIdx.x;   // 16384 threads
    if (i < N4H) {
        int o = ((i & 3) << 9) + (i >> 2);
        bsum0p[i] = b_ih0[o] + b_hh0[o];
        bsum1p[i] = b_ih1[o] + b_hh1[o];
        wrowp[i]  = wih0_row0[o];
    }
    if (i < 32 * HH) {
        int k = i & (HH - 1);
        int c = i >> 9;
        Wo1t[i] = Wo1[(size_t)k * 32 + c];
        Wg1t[i] = Wg1[(size_t)k * 32 + c];
    }
}

// ===========================================================================
// head: out[b*stride] = sigmoid(relu(h1@W1+b1)@W2+b2); h1 bf16 strided,
// W1t pre-transposed [32][512].
// ===========================================================================
__global__ void head_kernel(const __nv_bfloat16* __restrict__ H1, int hld,
                            const float* __restrict__ W1t,
                            const float* __restrict__ b1,
                            const float* __restrict__ W2,
                            const float* __restrict__ b2,
                            float* __restrict__ out, int out_stride,
                            float* __restrict__ intent_next)
{
    int gwarp = (blockIdx.x * blockDim.x + threadIdx.x) >> 5;
    int lane  = threadIdx.x & 31;
    if (gwarp >= BB) return;
    const uint4*  h4 = (const uint4*)(H1 + (size_t)gwarp * hld);    // 8 halfs
    const float4* w4 = (const float4*)(W1t + lane * HH);
    float a0 = 0.f, a1 = 0.f, a2 = 0.f, a3 = 0.f;
    #pragma unroll 8
    for (int k = 0; k < HH / 8; ++k) {
        uint4 hv = __ldg(h4 + k);
        float4 w0 = __ldg(w4 + 2 * k);
        float4 w1 = __ldg(w4 + 2 * k + 1);
        float2 f;
        f = __bfloat1622float2(*(__nv_bfloat162*)&hv.x);
        a0 = fmaf(f.x, w0.x, a0); a1 = fmaf(f.y, w0.y, a1);
        f = __bfloat1622float2(*(__nv_bfloat162*)&hv.y);
        a2 = fmaf(f.x, w0.z, a2); a3 = fmaf(f.y, w0.w, a3);
        f = __bfloat1622float2(*(__nv_bfloat162*)&hv.z);
        a0 = fmaf(f.x, w1.x, a0); a1 = fmaf(f.y, w1.y, a1);
        f = __bfloat1622float2(*(__nv_bfloat162*)&hv.w);
        a2 = fmaf(f.x, w1.z, a2); a3 = fmaf(f.y, w1.w, a3);
    }
    float acc = ((a0 + a1) + (a2 + a3)) + b1[lane];
    acc = fmaxf(acc, 0.f);
    float v = acc * W2[lane];
    #pragma unroll
    for (int off = 16; off; off >>= 1)
        v += __shfl_xor_sync(0xffffffffu, v, off);
    if (lane == 0) {
        float logit = v + b2[0];
        float it = 1.f / (1.f + expf(-logit));
        out[(size_t)gwarp * out_stride] = it;
        if (intent_next) intent_next[gwarp] = it;
    }
}

// ===========================================================================
extern "C" void kernel_launch(void* const* d_in, const int* in_sizes, int n_in,
                              void* d_out, int out_size)
{
    const float* encoder = (const float*)d_in[0];
    const float* context = (const float*)d_in[1];
    const float* init_it = (const float*)d_in[2];
    const float* Wh_init = (const float*)d_in[3];
    const float* bh_init = (const float*)d_in[4];
    const float* Wc_init = (const float*)d_in[5];
    const float* bc_init = (const float*)d_in[6];
    const float* W_ih0   = (const float*)d_in[7];
    const float* W_hh0   = (const float*)d_in[8];
    const float* b_ih0   = (const float*)d_in[9];
    const float* b_hh0   = (const float*)d_in[10];
    const float* W_ih1   = (const float*)d_in[11];
    const float* W_hh1   = (const float*)d_in[12];
    const float* b_ih1   = (const float*)d_in[13];
    const float* b_hh1   = (const float*)d_in[14];
    const float* Wo1     = (const float*)d_in[15];
    const float* bo1     = (const float*)d_in[16];
    const float* Wo2     = (const float*)d_in[17];
    const float* bo2     = (const float*)d_in[18];
    const float* Wg1     = (const float*)d_in[19];
    const float* bg1     = (const float*)d_in[20];
    const float* Wg2     = (const float*)d_in[21];
    const float* bg2     = (const float*)d_in[22];
    float* out = (float*)d_out;

    float *C01, *intent, *bsum0p, *bsum1p, *wrowp, *Wo1t, *Wg1t;
    cudaGetSymbolAddress((void**)&C01, g_C01);
    cudaGetSymbolAddress((void**)&intent, g_intent);
    cudaGetSymbolAddress((void**)&bsum0p, g_bsum0p);
    cudaGetSymbolAddress((void**)&bsum1p, g_bsum1p);
    cudaGetSymbolAddress((void**)&wrowp,  g_wrowp);
    cudaGetSymbolAddress((void**)&Wo1t,   g_Wo1t);
    cudaGetSymbolAddress((void**)&Wg1t,   g_Wg1t);

    __nv_bfloat16 *Xcb, *bH01, *bEnc, *bCtx, *bWh, *bWc, *bWi0c, *bWhh0, *bW1s;
    cudaGetSymbolAddress((void**)&Xcb,  g_Xcb);
    cudaGetSymbolAddress((void**)&bH01, g_bH01);
    cudaGetSymbolAddress((void**)&bEnc, g_bEnc);
    cudaGetSymbolAddress((void**)&bCtx, g_bCtx);
    cudaGetSymbolAddress((void**)&bWh,  g_bWh);
    cudaGetSymbolAddress((void**)&bWc,  g_bWc);
    cudaGetSymbolAddress((void**)&bWi0c, g_bWi0c);
    cudaGetSymbolAddress((void**)&bWhh0, g_bWhh0);
    cudaGetSymbolAddress((void**)&bW1s,  g_bW1s);

    cudaFuncSetAttribute(gemm_step, cudaFuncAttributeMaxDynamicSharedMemorySize,
                         DYN_SMEM);

    // ---- setup ----
    cvt_all_kernel<<<1024, 256>>>(encoder, context, Wh_init, Wc_init,
                                  bEnc, bCtx, bWh, bWc);
    cvt_perm_kernel<<<2048, 256>>>(W_hh0, W_ih1, W_hh1, W_ih0,
                                   bWhh0, bW1s, bWi0c);
    misc_prep_kernel<<<64, 256>>>(b_ih0, b_hh0, b_ih1, b_hh1, W_ih0,
                                  Wo1, Wg1,
                                  bsum0p, bsum1p, wrowp, Wo1t, Wg1t);

    // ---- init: [h0|h1] = enc@Wh + bh ; [c0|c1] = enc@Wc + bc (stacked) ----
    dim3 gridInit(2 * HH / IBN, BB / IBM);   // (8, 32)
    gemm_init<<<gridInit, 256>>>(bEnc, DD, bWh, 2 * HH, DD, bh_init,
                                 nullptr, bH01, 2 * HH);
    gemm_init<<<gridInit, 256>>>(bEnc, DD, bWc, 2 * HH, DD, bc_init,
                                 C01, nullptr, 2 * HH);

    // ---- Xc (bf16) = ctx @ bWi0c + bsum0p ----
    dim3 gridStep(N4H / BN, BB / BM);        // (16, 32)
    gemm_step<<<gridStep, 512, DYN_SMEM>>>(bCtx, DD, bWi0c, N4H, DD,
                                           bsum0p, nullptr, nullptr, nullptr,
                                           Xcb, N4H,
                                           nullptr, 0, 0, nullptr, 0, 0);

    // ---- time loop: 3 launches per step ----
    for (int t = 0; t < TT; ++t) {
        const float* it = (t == 0) ? init_it : intent;

        // layer0: gates = h0 @ bWhh0 + Xcb + intent*wrow -> fused cell (c0,h0)
        gemm_step<<<gridStep, 512, DYN_SMEM>>>(bH01, 2 * HH, bWhh0, N4H, HH,
                                               nullptr, Xcb, it, wrowp,
                                               nullptr, 0,
                                               C01, 2 * HH, 0,
                                               bH01, 2 * HH, 0);

        // layer1: gates = [h0n|h1] @ bW1s + bsum1p -> fused cell (c1,h1)
        gemm_step<<<gridStep, 512, DYN_SMEM>>>(bH01, 2 * HH, bW1s, N4H, 2 * HH,
                                               bsum1p, nullptr, nullptr, nullptr,
                                               nullptr, 0,
                                               C01, 2 * HH, HH,
                                               bH01, 2 * HH, HH);

        head_kernel<<<BB / 8, 256>>>(bH01 + HH, 2 * HH, Wo1t, bo1, Wo2, bo2,
                                     out + t, TT, intent);
    }

    head_kernel<<<BB / 8, 256>>>(bH01 + HH, 2 * HH, Wg1t, bg1, Wg2, bg2,
                                 out + (size_t)BB * TT, 1, nullptr);
}

// round 16
// speedup vs baseline: 1.4104x; 1.4104x over previous
#include <cuda_runtime.h>
#include <cuda_bf16.h>
#include <math.h>
#include <stdint.h>

// Problem constants
#define BB 4096
#define DD 256
#define HH 512
#define TT 45
#define N4H 2048

// step-GEMM tile config: 512 threads, warp grid 4x4, warp tile 32x32
#define BM 128
#define BN 128
#define BK 32
#define LDA_H 40     // As row stride halfs (80B) - conflict-free ldmatrix
#define LDB_H 136    // Bs row stride halfs (272B) - conflict-free
#define NSTG 3
#define STG_A (BM * LDA_H * 2)          // 10240 B
#define STG_BB (BK * LDB_H * 2)         // 8704 B
#define STG_SZ (STG_A + STG_BB)         // 18944 B
#define CS_LD 36                        // c-tile row stride (f32; 144B)
#define CS_OFF (NSTG * STG_SZ)          // 56832
#define CS_BYTES (BM * CS_LD * 4)       // 18432
#define DYN_SMEM (CS_OFF + CS_BYTES)    // 75264  -> 2 CTAs/SM

// ---------------- scratch ----------------
__device__ float g_C01[BB * 2 * HH];            // [B][1024]: c0 | c1
__device__ float g_intent[BB];
__device__ float g_bsum0p[N4H];
__device__ float g_bsum1p[N4H];
__device__ float g_wrowp [N4H];

__device__ __nv_bfloat16 g_Xcb [BB * N4H];      // bf16 Xc
__device__ __nv_bfloat16 g_bH01[BB * 2 * HH];   // [B][1024]: h0 | h1
__device__ __nv_bfloat16 g_bEnc [BB * DD];
__device__ __nv_bfloat16 g_bCtx [BB * DD];
__device__ __nv_bfloat16 g_bWh  [DD * 2 * HH];
__device__ __nv_bfloat16 g_bWc  [DD * 2 * HH];
__device__ __nv_bfloat16 g_bWi0c[DD * N4H];     // [256][2048] perm
__device__ __nv_bfloat16 g_bWhh0[HH * N4H];     // [512][2048] perm
__device__ __nv_bfloat16 g_bW1s [2 * HH * N4H]; // [1024][2048]: Wih1|Whh1 perm

// ---------------- low-level helpers ----------------
__device__ __forceinline__ uint32_t smem_u32(const void* p) {
    uint32_t a;
    asm("{ .reg .u64 t; cvta.to.shared.u64 t, %1; cvt.u32.u64 %0, t; }"
        : "=r"(a) : "l"(p));
    return a;
}
__device__ __forceinline__ void cp16(uint32_t dst_sh, const void* src) {
    asm volatile("cp.async.cg.shared.global [%0], [%1], 16;\n"
                 :: "r"(dst_sh), "l"(src));
}
#define CP_COMMIT() asm volatile("cp.async.commit_group;\n" ::: "memory")
template <int N>
__device__ __forceinline__ void cp_wait() {
    asm volatile("cp.async.wait_group %0;\n" :: "n"(N) : "memory");
}
__device__ __forceinline__ void ldm_x4(uint32_t r[4], uint32_t addr) {
    asm volatile("ldmatrix.sync.aligned.m8n8.x4.shared.b16 {%0,%1,%2,%3}, [%4];\n"
                 : "=r"(r[0]), "=r"(r[1]), "=r"(r[2]), "=r"(r[3]) : "r"(addr));
}
__device__ __forceinline__ void ldm_x4t(uint32_t r[4], uint32_t addr) {
    asm volatile("ldmatrix.sync.aligned.m8n8.x4.trans.shared.b16 {%0,%1,%2,%3}, [%4];\n"
                 : "=r"(r[0]), "=r"(r[1]), "=r"(r[2]), "=r"(r[3]) : "r"(addr));
}
__device__ __forceinline__ void mma_bf16(float c[4], const uint32_t a[4],
                                         uint32_t b0, uint32_t b1) {
    asm volatile(
        "mma.sync.aligned.m16n8k16.row.col.f32.bf16.bf16.f32 "
        "{%0,%1,%2,%3}, {%4,%5,%6,%7}, {%8,%9}, {%0,%1,%2,%3};\n"
        : "+f"(c[0]), "+f"(c[1]), "+f"(c[2]), "+f"(c[3])
        : "r"(a[0]), "r"(a[1]), "r"(a[2]), "r"(a[3]), "r"(b0), "r"(b1));
}
__device__ __forceinline__ float tanh_fast(float x) {
    float y; asm("tanh.approx.f32 %0, %1;" : "=f"(y) : "f"(x)); return y;
}
__device__ __forceinline__ float sig_fast(float x) {
    return fmaf(tanh_fast(0.5f * x), 0.5f, 0.5f);
}

// ===========================================================================
// Step GEMM (512 threads, 3-stage pipeline, 1 sync/K-tile, c-tile prefetch):
// V[m,n] = sum_k A[m,k]*B[k,n] + bias[n] (+ Xaddb[m,n] + intent[m]*wrow[n])
// cell_c==null: plain: V -> Xout (bf16, ld xo_ld).
// cell_c!=null: gate-interleaved fused LSTM cell (SMEM-staged; c prefetched
//   via cp.async at kernel start). Xaddb read from global in epilogue.
// ===========================================================================
__global__ __launch_bounds__(512, 2)
void gemm_step(const __nv_bfloat16* __restrict__ A, int lda,
               const __nv_bfloat16* __restrict__ B, int ldb, int K,
               const float* __restrict__ bias,
               const __nv_bfloat16* __restrict__ Xaddb,
               const float* __restrict__ intent,
               const float* __restrict__ wrow,
               __nv_bfloat16* __restrict__ Xout, int xo_ld,
               float* __restrict__ cell_c, int cc_ld, int cc_off,
               __nv_bfloat16* __restrict__ Hb, int hb_ld, int hb_off)
{
    extern __shared__ __align__(16) char smraw[];

    const int tid  = threadIdx.x;
    const int lane = tid & 31;
    const int wid  = tid >> 5;              // 0..15
    const int wm   = (wid & 3) * 32;
    const int wn   = (wid >> 2) * 32;
    const int g    = lane >> 2;
    const int t    = lane & 3;
    const int m0   = blockIdx.y * BM;
    const int n0   = blockIdx.x * BN;
    const int hid0 = n0 >> 2;

    const uint32_t smb = smem_u32(smraw);

    // c-tile prefetch (own commit group, FIRST) -- rides under the mainloop
    if (cell_c) {
        #pragma unroll
        for (int k2 = 0; k2 < 2; ++k2) {
            int idx = tid + k2 * 512;       // 1024 segs = 128 rows x 8
            int r = idx >> 3, s = idx & 7;
            cp16(smb + CS_OFF + r * (CS_LD * 4) + s * 16,
                 cell_c + (size_t)(m0 + r) * cc_ld + cc_off + hid0 + s * 4);
        }
        CP_COMMIT();
    }

    float acc[2][4][4];
    #pragma unroll
    for (int mi = 0; mi < 2; ++mi)
        #pragma unroll
        for (int ni = 0; ni < 4; ++ni)
            #pragma unroll
            for (int r = 0; r < 4; ++r) acc[mi][ni][r] = 0.f;

    // loaders (one cp16 each for A and B)
    const int arow = tid >> 2;              // 0..127
    const int acol = (tid & 3) * 8;         // halfs
    const int brow = tid >> 4;              // 0..31
    const int bcol = (tid & 15) * 8;        // halfs
    const int ktotal = K / BK;

    auto issue = [&](int kt) {
        const uint32_t base = smb + (kt % NSTG) * STG_SZ;
        cp16(base + (arow * LDA_H + acol) * 2,
             A + (size_t)(m0 + arow) * lda + kt * BK + acol);
        cp16(base + STG_A + (brow * LDB_H + bcol) * 2,
             B + (size_t)(kt * BK + brow) * ldb + n0 + bcol);
        CP_COMMIT();
    };

    issue(0);
    if (ktotal > 1) issue(1);

    const int a_lrow = lane & 15;
    const int a_lcol = (lane >> 4) << 3;
    const int b_lrow = (lane & 7) + (lane & 8);
    const int b_lcol = (lane >> 4) << 3;

    #pragma unroll 1
    for (int kt = 0; kt < ktotal; ++kt) {
        if (kt + 1 < ktotal) cp_wait<1>(); else cp_wait<0>();
        __syncthreads();
        if (kt + 2 < ktotal) issue(kt + 2);

        const uint32_t sb = smb + (kt % NSTG) * STG_SZ;
        const uint32_t asb = sb;
        const uint32_t bsb = sb + STG_A;

        #pragma unroll
        for (int kk = 0; kk < 2; ++kk) {
            const int kc = kk * 16;
            uint32_t afr[2][4];
            #pragma unroll
            for (int mi = 0; mi < 2; ++mi)
                ldm_x4(afr[mi], asb + ((wm + mi * 16 + a_lrow) * LDA_H + kc + a_lcol) * 2);
            uint32_t bfr[4][2];
            #pragma unroll
            for (int nj = 0; nj < 2; ++nj) {
                uint32_t r[4];
                ldm_x4t(r, bsb + ((kc + b_lrow) * LDB_H + wn + nj * 16 + b_lcol) * 2);
                bfr[nj*2+0][0] = r[0]; bfr[nj*2+0][1] = r[1];
                bfr[nj*2+1][0] = r[2]; bfr[nj*2+1][1] = r[3];
            }
            #pragma unroll
            for (int mi = 0; mi < 2; ++mi)
                #pragma unroll
                for (int ni = 0; ni < 4; ++ni)
                    mma_bf16(acc[mi][ni], afr[mi], bfr[ni][0], bfr[ni][1]);
        }
    }

    // ---------------- epilogue ----------------
    if (cell_c == nullptr) {
        // plain path: bias + bf16 store (used for Xc precompute)
        #pragma unroll
        for (int mi = 0; mi < 2; ++mi) {
            const int row0 = m0 + wm + mi * 16 + g;
            const int row1 = row0 + 8;
            #pragma unroll
            for (int ni = 0; ni < 4; ++ni) {
                const int col = n0 + wn + ni * 8 + t * 2;
                float b0 = bias ? bias[col] : 0.f;
                float b1 = bias ? bias[col + 1] : 0.f;
                float v00 = acc[mi][ni][0] + b0;
                float v01 = acc[mi][ni][1] + b1;
                float v10 = acc[mi][ni][2] + b0;
                float v11 = acc[mi][ni][3] + b1;
                *(__nv_bfloat162*)(Xout + (size_t)row0 * xo_ld + col) =
                    __nv_bfloat162(__float2bfloat16(v00), __float2bfloat16(v01));
                *(__nv_bfloat162*)(Xout + (size_t)row1 * xo_ld + col) =
                    __nv_bfloat162(__float2bfloat16(v10), __float2bfloat16(v11));
            }
        }
        return;
    }

    // fused cell path: c tile already in smem (prefetched); hs overlays stages
    __syncthreads();   // all warps done with stage-region ldmatrix reads
    float* cs = (float*)(smraw + CS_OFF);                   // [128][36] f32
    __nv_bfloat16* hs = (__nv_bfloat16*)smraw;              // [128][36] bf16

    const bool evenT = ((t & 1) == 0);
    const bool useX = (Xaddb != nullptr);
    #pragma unroll
    for (int mi = 0; mi < 2; ++mi) {
        const int r0 = wm + mi * 16 + g;
        const int r1 = r0 + 8;
        const float it0 = intent ? intent[m0 + r0] : 0.f;
        const float it1 = intent ? intent[m0 + r1] : 0.f;
        #pragma unroll
        for (int ni = 0; ni < 4; ++ni) {
            const int lcol = wn + ni * 8 + t * 2;
            const int col  = n0 + lcol;
            const int hidl = lcol >> 2;
            float b0 = bias ? bias[col] : 0.f;
            float b1 = bias ? bias[col + 1] : 0.f;
            float v00 = acc[mi][ni][0] + b0;
            float v01 = acc[mi][ni][1] + b1;
            float v10 = acc[mi][ni][2] + b0;
            float v11 = acc[mi][ni][3] + b1;
            if (intent) {
                float w0 = wrow[col], w1 = wrow[col + 1];
                v00 = fmaf(it0, w0, v00); v01 = fmaf(it0, w1, v01);
                v10 = fmaf(it1, w0, v10); v11 = fmaf(it1, w1, v11);
            }
            if (useX) {
                float2 x0 = __bfloat1622float2(
                    *(const __nv_bfloat162*)(Xaddb + (size_t)(m0 + r0) * N4H + col));
                float2 x1 = __bfloat1622float2(
                    *(const __nv_bfloat162*)(Xaddb + (size_t)(m0 + r1) * N4H + col));
                v00 += x0.x; v01 += x0.y; v10 += x1.x; v11 += x1.y;
            }

            // even t: (i,f); odd t: (g,o)
            float a0, a1;
            if (evenT) { a0 = sig_fast(v00);  a1 = sig_fast(v10); }
            else       { a0 = tanh_fast(v00); a1 = tanh_fast(v10); }
            float bv0 = sig_fast(v01);
            float bv1 = sig_fast(v11);

            float pa0 = __shfl_xor_sync(0xffffffffu, a0, 1);
            float pa1 = __shfl_xor_sync(0xffffffffu, a1, 1);

            float tc0 = 0.f, tc1 = 0.f;
            if (evenT) {
                float cn0 = fmaf(bv0, cs[r0 * CS_LD + hidl], a0 * pa0);
                float cn1 = fmaf(bv1, cs[r1 * CS_LD + hidl], a1 * pa1);
                cs[r0 * CS_LD + hidl] = cn0;
                cs[r1 * CS_LD + hidl] = cn1;
                tc0 = tanh_fast(cn0);
                tc1 = tanh_fast(cn1);
            }
            float q0 = __shfl_xor_sync(0xffffffffu, tc0, 1);
            float q1 = __shfl_xor_sync(0xffffffffu, tc1, 1);
            if (!evenT) {
                hs[r0 * CS_LD + hidl] = __float2bfloat16(bv0 * q0);
                hs[r1 * CS_LD + hidl] = __float2bfloat16(bv1 * q1);
            }
        }
    }
    __syncthreads();

    // coalesced store of c and h tiles
    #pragma unroll 2
    for (int i = tid; i < BM * 32; i += 512) {
        int r = i >> 5, cc = i & 31;
        cell_c[(size_t)(m0 + r) * cc_ld + cc_off + hid0 + cc] = cs[r * CS_LD + cc];
        Hb[(size_t)(m0 + r) * hb_ld + hb_off + hid0 + cc]     = hs[r * CS_LD + cc];
    }
}

// ===========================================================================
// init GEMM (256 threads, plain epilogue): C = A@B + bias
// ===========================================================================
#define IBM 128
#define IBN 128
#define IBK 32

__global__ __launch_bounds__(256, 2)
void gemm_init(const __nv_bfloat16* __restrict__ A, int lda,
               const __nv_bfloat16* __restrict__ B, int ldb, int K,
               const float* __restrict__ bias,
               float* __restrict__ C,
               __nv_bfloat16* __restrict__ Cb, int ldc)
{
    __shared__ __nv_bfloat16 As[2][IBM * LDA_H];
    __shared__ __nv_bfloat16 Bs[2][IBK * LDB_H];

    const int tid  = threadIdx.x;
    const int lane = tid & 31;
    const int wid  = tid >> 5;
    const int wm   = (wid & 1) * 64;
    const int wn   = (wid >> 1) * 32;
    const int g    = lane >> 2;
    const int t    = lane & 3;
    const int m0   = blockIdx.y * IBM;
    const int n0   = blockIdx.x * IBN;

    const uint32_t as_base = smem_u32(&As[0][0]);
    const uint32_t bs_base = smem_u32(&Bs[0][0]);
    const uint32_t as_sz = IBM * LDA_H * 2;
    const uint32_t bs_sz = IBK * LDB_H * 2;

    float acc[4][4][4];
    #pragma unroll
    for (int mi = 0; mi < 4; ++mi)
        #pragma unroll
        for (int ni = 0; ni < 4; ++ni)
            #pragma unroll
            for (int r = 0; r < 4; ++r) acc[mi][ni][r] = 0.f;

    const int arow = tid >> 1;
    const int aoff = (tid & 1) * 16;
    const int brow = tid >> 4;
    const int boff = (tid & 15) * 8;
    const int ktotal = K / IBK;

    auto issue = [&](int kt, int b) {
        const __nv_bfloat16* asrc = A + (size_t)(m0 + arow) * lda + kt * IBK + aoff;
        uint32_t adst = as_base + b * as_sz + (arow * LDA_H + aoff) * 2;
        cp16(adst, asrc);
        cp16(adst + 16, asrc + 8);
        const __nv_bfloat16* bsrc = B + (size_t)(kt * IBK + brow) * ldb + n0 + boff;
        uint32_t bdst = bs_base + b * bs_sz + (brow * LDB_H + boff) * 2;
        cp16(bdst, bsrc);
        cp16(bdst + 16 * LDB_H * 2, bsrc + (size_t)16 * ldb);
    };

    issue(0, 0);
    CP_COMMIT();

    const int a_lrow = lane & 15;
    const int a_lcol = (lane >> 4) << 3;
    const int b_lrow = (lane & 7) + (lane & 8);
    const int b_lcol = (lane >> 4) << 3;

    #pragma unroll 1
    for (int kt = 0; kt < ktotal; ++kt) {
        if (kt + 1 < ktotal) {
            issue(kt + 1, (kt + 1) & 1);
            CP_COMMIT();
            cp_wait<1>();
        } else {
            cp_wait<0>();
        }
        __syncthreads();

        const int b = kt & 1;
        const uint32_t asb = as_base + b * as_sz;
        const uint32_t bsb = bs_base + b * bs_sz;

        #pragma unroll
        for (int kk = 0; kk < 2; ++kk) {
            const int kc = kk * 16;
            uint32_t afr[4][4];
            #pragma unroll
            for (int mi = 0; mi < 4; ++mi)
                ldm_x4(afr[mi], asb + ((wm + mi * 16 + a_lrow) * LDA_H + kc + a_lcol) * 2);
            uint32_t bfr[4][2];
            #pragma unroll
            for (int nj = 0; nj < 2; ++nj) {
                uint32_t r[4];
                ldm_x4t(r, bsb + ((kc + b_lrow) * LDB_H + wn + nj * 16 + b_lcol) * 2);
                bfr[nj*2+0][0] = r[0]; bfr[nj*2+0][1] = r[1];
                bfr[nj*2+1][0] = r[2]; bfr[nj*2+1][1] = r[3];
            }
            #pragma unroll
            for (int mi = 0; mi < 4; ++mi)
                #pragma unroll
                for (int ni = 0; ni < 4; ++ni)
                    mma_bf16(acc[mi][ni], afr[mi], bfr[ni][0], bfr[ni][1]);
        }
        __syncthreads();
    }

    #pragma unroll
    for (int mi = 0; mi < 4; ++mi) {
        const int row0 = m0 + wm + mi * 16 + g;
        const int row1 = row0 + 8;
        #pragma unroll
        for (int ni = 0; ni < 4; ++ni) {
            const int col = n0 + wn + ni * 8 + t * 2;
            float b0 = bias ? bias[col] : 0.f;
            float b1 = bias ? bias[col + 1] : 0.f;
            float v00 = acc[mi][ni][0] + b0;
            float v01 = acc[mi][ni][1] + b1;
            float v10 = acc[mi][ni][2] + b0;
            float v11 = acc[mi][ni][3] + b1;
            if (C) {
                *(float2*)(C + (size_t)row0 * ldc + col) = make_float2(v00, v01);
                *(float2*)(C + (size_t)row1 * ldc + col) = make_float2(v10, v11);
            }
            if (Cb) {
                *(__nv_bfloat162*)(Cb + (size_t)row0 * ldc + col) =
                    __nv_bfloat162(__float2bfloat16(v00), __float2bfloat16(v01));
                *(__nv_bfloat162*)(Cb + (size_t)row1 * ldc + col) =
                    __nv_bfloat162(__float2bfloat16(v10), __float2bfloat16(v11));
            }
        }
    }
}

// ===========================================================================
// setup kernels
// ===========================================================================
__global__ void cvt_all_kernel(const float* __restrict__ enc,
                               const float* __restrict__ ctx,
                               const float* __restrict__ Wh,
                               const float* __restrict__ Wc,
                               __nv_bfloat16* __restrict__ bEnc,
                               __nv_bfloat16* __restrict__ bCtx,
                               __nv_bfloat16* __restrict__ bWh,
                               __nv_bfloat16* __restrict__ bWc)
{
    const int n1 = BB * DD, n2 = DD * 2 * HH;
    int i = blockIdx.x * blockDim.x + threadIdx.x;
    int stride = gridDim.x * blockDim.x;
    int total = 2 * n1 + 2 * n2;
    for (; i < total; i += stride) {
        if (i < n1)               bEnc[i]              = __float2bfloat16(enc[i]);
        else if (i < 2 * n1)      bCtx[i - n1]         = __float2bfloat16(ctx[i - n1]);
        else if (i < 2 * n1 + n2) bWh[i - 2 * n1]      = __float2bfloat16(Wh[i - 2 * n1]);
        else                      bWc[i - 2 * n1 - n2] = __float2bfloat16(Wc[i - 2 * n1 - n2]);
    }
}

// gate-interleave permutation of K x 2048 weight matrices into bf16
__global__ void cvt_perm_kernel(const float* __restrict__ Whh0,
                                const float* __restrict__ Wih1,
                                const float* __restrict__ Whh1,
                                const float* __restrict__ Wih0,
                                __nv_bfloat16* __restrict__ bWhh0,
                                __nv_bfloat16* __restrict__ bW1s,
                                __nv_bfloat16* __restrict__ bWi0c)
{
    int i = blockIdx.x * blockDim.x + threadIdx.x;
    int stride = gridDim.x * blockDim.x;
    const int nA = HH * N4H;
    const int nB = HH * N4H;
    const int nC = HH * N4H;
    const int nD = DD * N4H;
    int total = nA + nB + nC + nD;
    for (; i < total; i += stride) {
        int j = i, k, c;
        const float* src;
        __nv_bfloat16* dst;
        if (j < nA)            { src = Whh0;  dst = bWhh0; }
        else if (j < nA + nB)  { j -= nA;  src = Wih1; dst = bW1s; }
        else if (j < nA+nB+nC) { j -= nA + nB; src = Whh1; dst = bW1s + (size_t)HH * N4H; }
        else                   { j -= nA + nB + nC; src = Wih0 + N4H; dst = bWi0c; }
        k = j >> 11;
        c = j & (N4H - 1);
        int o = ((c & 3) << 9) + (c >> 2);
        dst[j] = __float2bfloat16(src[(size_t)k * N4H + o]);
    }
}

__global__ void bias_prep_kernel(const float* __restrict__ b_ih0,
                                 const float* __restrict__ b_hh0,
                                 const float* __restrict__ b_ih1,
                                 const float* __restrict__ b_hh1,
                                 const float* __restrict__ wih0_row0,
                                 float* __restrict__ bsum0p,
                                 float* __restrict__ bsum1p,
                                 float* __restrict__ wrowp)
{
    int c = blockIdx.x * blockDim.x + threadIdx.x;
    if (c >= N4H) return;
    int o = ((c & 3) << 9) + (c >> 2);
    bsum0p[c] = b_ih0[o] + b_hh0[o];
    bsum1p[c] = b_ih1[o] + b_hh1[o];
    wrowp[c]  = wih0_row0[o];
}

// ===========================================================================
// head: out[b*stride] = sigmoid(relu(h1@W1+b1)@W2+b2); h1 bf16 strided.
// W1 ORIGINAL layout [512][32] (lane = output col, coalesced + broadcast);
// 4 independent accumulator chains.
// ===========================================================================
__global__ void head_kernel(const __nv_bfloat16* __restrict__ H1, int hld,
                            const float* __restrict__ W1,
                            const float* __restrict__ b1,
                            const float* __restrict__ W2,
                            const float* __restrict__ b2,
                            float* __restrict__ out, int out_stride,
                            float* __restrict__ intent_next)
{
    int gwarp = (blockIdx.x * blockDim.x + threadIdx.x) >> 5;
    int lane  = threadIdx.x & 31;
    if (gwarp >= BB) return;
    const uint4* h4 = (const uint4*)(H1 + (size_t)gwarp * hld);    // 8 halfs
    float a0 = 0.f, a1 = 0.f, a2 = 0.f, a3 = 0.f;
    #pragma unroll 4
    for (int k8 = 0; k8 < HH / 8; ++k8) {
        uint4 hv = __ldg(h4 + k8);
        const float* wr = W1 + (k8 * 8) * 32 + lane;
        float2 f;
        f = __bfloat1622float2(*(__nv_bfloat162*)&hv.x);
        a0 = fmaf(f.x, __ldg(wr + 0 * 32), a0);
        a1 = fmaf(f.y, __ldg(wr + 1 * 32), a1);
        f = __bfloat1622float2(*(__nv_bfloat162*)&hv.y);
        a2 = fmaf(f.x, __ldg(wr + 2 * 32), a2);
        a3 = fmaf(f.y, __ldg(wr + 3 * 32), a3);
        f = __bfloat1622float2(*(__nv_bfloat162*)&hv.z);
        a0 = fmaf(f.x, __ldg(wr + 4 * 32), a0);
        a1 = fmaf(f.y, __ldg(wr + 5 * 32), a1);
        f = __bfloat1622float2(*(__nv_bfloat162*)&hv.w);
        a2 = fmaf(f.x, __ldg(wr + 6 * 32), a2);
        a3 = fmaf(f.y, __ldg(wr + 7 * 32), a3);
    }
    float acc = ((a0 + a1) + (a2 + a3)) + b1[lane];
    acc = fmaxf(acc, 0.f);
    float v = acc * W2[lane];
    #pragma unroll
    for (int off = 16; off; off >>= 1)
        v += __shfl_xor_sync(0xffffffffu, v, off);
    if (lane == 0) {
        float logit = v + b2[0];
        float it = 1.f / (1.f + expf(-logit));
        out[(size_t)gwarp * out_stride] = it;
        if (intent_next) intent_next[gwarp] = it;
    }
}

// ===========================================================================
extern "C" void kernel_launch(void* const* d_in, const int* in_sizes, int n_in,
                              void* d_out, int out_size)
{
    const float* encoder = (const float*)d_in[0];
    const float* context = (const float*)d_in[1];
    const float* init_it = (const float*)d_in[2];
    const float* Wh_init = (const float*)d_in[3];
    const float* bh_init = (const float*)d_in[4];
    const float* Wc_init = (const float*)d_in[5];
    const float* bc_init = (const float*)d_in[6];
    const float* W_ih0   = (const float*)d_in[7];
    const float* W_hh0   = (const float*)d_in[8];
    const float* b_ih0   = (const float*)d_in[9];
    const float* b_hh0   = (const float*)d_in[10];
    const float* W_ih1   = (const float*)d_in[11];
    const float* W_hh1   = (const float*)d_in[12];
    const float* b_ih1   = (const float*)d_in[13];
    const float* b_hh1   = (const float*)d_in[14];
    const float* Wo1     = (const float*)d_in[15];
    const float* bo1     = (const float*)d_in[16];
    const float* Wo2     = (const float*)d_in[17];
    const float* bo2     = (const float*)d_in[18];
    const float* Wg1     = (const float*)d_in[19];
    const float* bg1     = (const float*)d_in[20];
    const float* Wg2     = (const float*)d_in[21];
    const float* bg2     = (const float*)d_in[22];
    float* out = (float*)d_out;

    float *C01, *intent, *bsum0p, *bsum1p, *wrowp;
    cudaGetSymbolAddress((void**)&C01, g_C01);
    cudaGetSymbolAddress((void**)&intent, g_intent);
    cudaGetSymbolAddress((void**)&bsum0p, g_bsum0p);
    cudaGetSymbolAddress((void**)&bsum1p, g_bsum1p);
    cudaGetSymbolAddress((void**)&wrowp,  g_wrowp);

    __nv_bfloat16 *Xcb, *bH01, *bEnc, *bCtx, *bWh, *bWc, *bWi0c, *bWhh0, *bW1s;
    cudaGetSymbolAddress((void**)&Xcb,  g_Xcb);
    cudaGetSymbolAddress((void**)&bH01, g_bH01);
    cudaGetSymbolAddress((void**)&bEnc, g_bEnc);
    cudaGetSymbolAddress((void**)&bCtx, g_bCtx);
    cudaGetSymbolAddress((void**)&bWh,  g_bWh);
    cudaGetSymbolAddress((void**)&bWc,  g_bWc);
    cudaGetSymbolAddress((void**)&bWi0c, g_bWi0c);
    cudaGetSymbolAddress((void**)&bWhh0, g_bWhh0);
    cudaGetSymbolAddress((void**)&bW1s,  g_bW1s);

    cudaFuncSetAttribute(gemm_step, cudaFuncAttributeMaxDynamicSharedMemorySize,
                         DYN_SMEM);

    // ---- setup ----
    cvt_all_kernel<<<1024, 256>>>(encoder, context, Wh_init, Wc_init,
                                  bEnc, bCtx, bWh, bWc);
    cvt_perm_kernel<<<2048, 256>>>(W_hh0, W_ih1, W_hh1, W_ih0,
                                   bWhh0, bW1s, bWi0c);
    bias_prep_kernel<<<8, 256>>>(b_ih0, b_hh0, b_ih1, b_hh1, W_ih0,
                                 bsum0p, bsum1p, wrowp);

    // ---- init: [h0|h1] = enc@Wh + bh ; [c0|c1] = enc@Wc + bc (stacked) ----
    dim3 gridInit(2 * HH / IBN, BB / IBM);   // (8, 32)
    gemm_init<<<gridInit, 256>>>(bEnc, DD, bWh, 2 * HH, DD, bh_init,
                                 nullptr, bH01, 2 * HH);
    gemm_init<<<gridInit, 256>>>(bEnc, DD, bWc, 2 * HH, DD, bc_init,
                                 C01, nullptr, 2 * HH);

    // ---- Xc (bf16) = ctx @ bWi0c + bsum0p ----
    dim3 gridStep(N4H / BN, BB / BM);        // (16, 32)
    gemm_step<<<gridStep, 512, DYN_SMEM>>>(bCtx, DD, bWi0c, N4H, DD,
                                           bsum0p, nullptr, nullptr, nullptr,
                                           Xcb, N4H,
                                           nullptr, 0, 0, nullptr, 0, 0);

    // ---- time loop: 3 launches per step ----
    for (int t = 0; t < TT; ++t) {
        const float* it = (t == 0) ? init_it : intent;

        // layer0: gates = h0 @ bWhh0 + Xcb + intent*wrow -> fused cell (c0,h0)
        gemm_step<<<gridStep, 512, DYN_SMEM>>>(bH01, 2 * HH, bWhh0, N4H, HH,
                                               nullptr, Xcb, it, wrowp,
                                               nullptr, 0,
                                               C01, 2 * HH, 0,
                                               bH01, 2 * HH, 0);

        // layer1: gates = [h0n|h1] @ bW1s + bsum1p -> fused cell (c1,h1)
        gemm_step<<<gridStep, 512, DYN_SMEM>>>(bH01, 2 * HH, bW1s, N4H, 2 * HH,
                                               bsum1p, nullptr, nullptr, nullptr,
                                               nullptr, 0,
                                               C01, 2 * HH, HH,
                                               bH01, 2 * HH, HH);

        head_kernel<<<BB / 8, 256>>>(bH01 + HH, 2 * HH, Wo1, bo1, Wo2, bo2,
                                     out + t, TT, intent);
    }

    head_kernel<<<BB / 8, 256>>>(bH01 + HH, 2 * HH, Wg1, bg1, Wg2, bg2,
                                 out + (size_t)BB * TT, 1, nullptr);
}

// round 17
// speedup vs baseline: 1.4472x; 1.0261x over previous
#include <cuda_runtime.h>
#include <cuda_bf16.h>
#include <math.h>
#include <stdint.h>

// Problem constants
#define BB 4096
#define DD 256
#define HH 512
#define TT 45
#define N4H 2048

// step-GEMM tile config: 512 threads, warp grid 4x4, warp tile 32x32
#define BM 128
#define BN 128
#define BK 32
#define LDA_H 40     // As row stride halfs (80B) - conflict-free ldmatrix
#define LDB_H 136    // Bs row stride halfs (272B) - conflict-free
#define NSTG 3
#define STG_A (BM * LDA_H * 2)          // 10240 B
#define STG_BB (BK * LDB_H * 2)         // 8704 B
#define STG_SZ (STG_A + STG_BB)         // 18944 B
#define CS_LD 36                        // c-tile row stride (f32; 144B)
#define CS_OFF (NSTG * STG_SZ)          // 56832
#define CS_BYTES (BM * CS_LD * 4)       // 18432
#define DYN_SMEM (CS_OFF + CS_BYTES)    // 75264  -> 2 CTAs/SM

// ---------------- scratch ----------------
__device__ float g_C01[BB * 2 * HH];            // [B][1024]: c0 | c1
__device__ float g_intent[BB];
__device__ float g_bsum0p[N4H];
__device__ float g_bsum1p[N4H];
__device__ float g_wrowp [N4H];

__device__ __nv_bfloat16 g_Xcb [BB * N4H];      // bf16 Xc
__device__ __nv_bfloat16 g_bH01[BB * 2 * HH];   // [B][1024]: h0 | h1
__device__ __nv_bfloat16 g_bEnc [BB * DD];
__device__ __nv_bfloat16 g_bCtx [BB * DD];
__device__ __nv_bfloat16 g_bWh  [DD * 2 * HH];
__device__ __nv_bfloat16 g_bWc  [DD * 2 * HH];
__device__ __nv_bfloat16 g_bWi0c[DD * N4H];     // [256][2048] perm
__device__ __nv_bfloat16 g_bWhh0[HH * N4H];     // [512][2048] perm
__device__ __nv_bfloat16 g_bW1s [2 * HH * N4H]; // [1024][2048]: Wih1|Whh1 perm

// ---------------- low-level helpers ----------------
__device__ __forceinline__ uint32_t smem_u32(const void* p) {
    uint32_t a;
    asm("{ .reg .u64 t; cvta.to.shared.u64 t, %1; cvt.u32.u64 %0, t; }"
        : "=r"(a) : "l"(p));
    return a;
}
__device__ __forceinline__ void cp16(uint32_t dst_sh, const void* src) {
    asm volatile("cp.async.cg.shared.global [%0], [%1], 16;\n"
                 :: "r"(dst_sh), "l"(src));
}
#define CP_COMMIT() asm volatile("cp.async.commit_group;\n" ::: "memory")
template <int N>
__device__ __forceinline__ void cp_wait() {
    asm volatile("cp.async.wait_group %0;\n" :: "n"(N) : "memory");
}
__device__ __forceinline__ void ldm_x4(uint32_t r[4], uint32_t addr) {
    asm volatile("ldmatrix.sync.aligned.m8n8.x4.shared.b16 {%0,%1,%2,%3}, [%4];\n"
                 : "=r"(r[0]), "=r"(r[1]), "=r"(r[2]), "=r"(r[3]) : "r"(addr));
}
__device__ __forceinline__ void ldm_x4t(uint32_t r[4], uint32_t addr) {
    asm volatile("ldmatrix.sync.aligned.m8n8.x4.trans.shared.b16 {%0,%1,%2,%3}, [%4];\n"
                 : "=r"(r[0]), "=r"(r[1]), "=r"(r[2]), "=r"(r[3]) : "r"(addr));
}
__device__ __forceinline__ void mma_bf16(float c[4], const uint32_t a[4],
                                         uint32_t b0, uint32_t b1) {
    asm volatile(
        "mma.sync.aligned.m16n8k16.row.col.f32.bf16.bf16.f32 "
        "{%0,%1,%2,%3}, {%4,%5,%6,%7}, {%8,%9}, {%0,%1,%2,%3};\n"
        : "+f"(c[0]), "+f"(c[1]), "+f"(c[2]), "+f"(c[3])
        : "r"(a[0]), "r"(a[1]), "r"(a[2]), "r"(a[3]), "r"(b0), "r"(b1));
}
__device__ __forceinline__ float tanh_fast(float x) {
    float y; asm("tanh.approx.f32 %0, %1;" : "=f"(y) : "f"(x)); return y;
}
__device__ __forceinline__ float sig_fast(float x) {
    return fmaf(tanh_fast(0.5f * x), 0.5f, 0.5f);
}

// ===========================================================================
// Step GEMM (512 threads, 3-stage pipeline, 1 sync/K-tile, c-tile prefetch):
// V[m,n] = sum_k A[m,k]*B[k,n] + bias[n] (+ Xaddb[m,n] + intent[m]*wrow[n])
// cell_c==null: plain: V -> Xout (bf16, ld xo_ld).
// cell_c!=null: gate-interleaved fused LSTM cell (SMEM-staged; c prefetched
//   via cp.async at kernel start). Xaddb read from global in epilogue.
// May be launched with PDL: cudaGridDependencySynchronize() before the
// epilogue (first consumption of the predecessor's output: intent/Xaddb).
// ===========================================================================
__global__ __launch_bounds__(512, 2)
void gemm_step(const __nv_bfloat16* __restrict__ A, int lda,
               const __nv_bfloat16* __restrict__ B, int ldb, int K,
               const float* __restrict__ bias,
               const __nv_bfloat16* __restrict__ Xaddb,
               const float* __restrict__ intent,
               const float* __restrict__ wrow,
               __nv_bfloat16* __restrict__ Xout, int xo_ld,
               float* __restrict__ cell_c, int cc_ld, int cc_off,
               __nv_bfloat16* __restrict__ Hb, int hb_ld, int hb_off)
{
    extern __shared__ __align__(16) char smraw[];

    const int tid  = threadIdx.x;
    const int lane = tid & 31;
    const int wid  = tid >> 5;              // 0..15
    const int wm   = (wid & 3) * 32;
    const int wn   = (wid >> 2) * 32;
    const int g    = lane >> 2;
    const int t    = lane & 3;
    const int m0   = blockIdx.y * BM;
    const int n0   = blockIdx.x * BN;
    const int hid0 = n0 >> 2;

    const uint32_t smb = smem_u32(smraw);

    // c-tile prefetch (own commit group, FIRST) -- rides under the mainloop
    if (cell_c) {
        #pragma unroll
        for (int k2 = 0; k2 < 2; ++k2) {
            int idx = tid + k2 * 512;       // 1024 segs = 128 rows x 8
            int r = idx >> 3, s = idx & 7;
            cp16(smb + CS_OFF + r * (CS_LD * 4) + s * 16,
                 cell_c + (size_t)(m0 + r) * cc_ld + cc_off + hid0 + s * 4);
        }
        CP_COMMIT();
    }

    float acc[2][4][4];
    #pragma unroll
    for (int mi = 0; mi < 2; ++mi)
        #pragma unroll
        for (int ni = 0; ni < 4; ++ni)
            #pragma unroll
            for (int r = 0; r < 4; ++r) acc[mi][ni][r] = 0.f;

    // loaders (one cp16 each for A and B)
    const int arow = tid >> 2;              // 0..127
    const int acol = (tid & 3) * 8;         // halfs
    const int brow = tid >> 4;              // 0..31
    const int bcol = (tid & 15) * 8;        // halfs
    const int ktotal = K / BK;

    auto issue = [&](int kt) {
        const uint32_t base = smb + (kt % NSTG) * STG_SZ;
        cp16(base + (arow * LDA_H + acol) * 2,
             A + (size_t)(m0 + arow) * lda + kt * BK + acol);
        cp16(base + STG_A + (brow * LDB_H + bcol) * 2,
             B + (size_t)(kt * BK + brow) * ldb + n0 + bcol);
        CP_COMMIT();
    };

    issue(0);
    if (ktotal > 1) issue(1);

    const int a_lrow = lane & 15;
    const int a_lcol = (lane >> 4) << 3;
    const int b_lrow = (lane & 7) + (lane & 8);
    const int b_lcol = (lane >> 4) << 3;

    #pragma unroll 1
    for (int kt = 0; kt < ktotal; ++kt) {
        if (kt + 1 < ktotal) cp_wait<1>(); else cp_wait<0>();
        __syncthreads();
        if (kt + 2 < ktotal) issue(kt + 2);

        const uint32_t sb = smb + (kt % NSTG) * STG_SZ;
        const uint32_t asb = sb;
        const uint32_t bsb = sb + STG_A;

        #pragma unroll
        for (int kk = 0; kk < 2; ++kk) {
            const int kc = kk * 16;
            uint32_t afr[2][4];
            #pragma unroll
            for (int mi = 0; mi < 2; ++mi)
                ldm_x4(afr[mi], asb + ((wm + mi * 16 + a_lrow) * LDA_H + kc + a_lcol) * 2);
            uint32_t bfr[4][2];
            #pragma unroll
            for (int nj = 0; nj < 2; ++nj) {
                uint32_t r[4];
                ldm_x4t(r, bsb + ((kc + b_lrow) * LDB_H + wn + nj * 16 + b_lcol) * 2);
                bfr[nj*2+0][0] = r[0]; bfr[nj*2+0][1] = r[1];
                bfr[nj*2+1][0] = r[2]; bfr[nj*2+1][1] = r[3];
            }
            #pragma unroll
            for (int mi = 0; mi < 2; ++mi)
                #pragma unroll
                for (int ni = 0; ni < 4; ++ni)
                    mma_bf16(acc[mi][ni], afr[mi], bfr[ni][0], bfr[ni][1]);
        }
    }

    // PDL: wait for predecessor (head writing intent) before epilogue reads.
    // No-op when not launched with programmatic stream serialization.
    cudaGridDependencySynchronize();

    // ---------------- epilogue ----------------
    if (cell_c == nullptr) {
        // plain path: bias + bf16 store (used for Xc precompute)
        #pragma unroll
        for (int mi = 0; mi < 2; ++mi) {
            const int row0 = m0 + wm + mi * 16 + g;
            const int row1 = row0 + 8;
            #pragma unroll
            for (int ni = 0; ni < 4; ++ni) {
                const int col = n0 + wn + ni * 8 + t * 2;
                float b0 = bias ? bias[col] : 0.f;
                float b1 = bias ? bias[col + 1] : 0.f;
                float v00 = acc[mi][ni][0] + b0;
                float v01 = acc[mi][ni][1] + b1;
                float v10 = acc[mi][ni][2] + b0;
                float v11 = acc[mi][ni][3] + b1;
                *(__nv_bfloat162*)(Xout + (size_t)row0 * xo_ld + col) =
                    __nv_bfloat162(__float2bfloat16(v00), __float2bfloat16(v01));
                *(__nv_bfloat162*)(Xout + (size_t)row1 * xo_ld + col) =
                    __nv_bfloat162(__float2bfloat16(v10), __float2bfloat16(v11));
            }
        }
        return;
    }

    // fused cell path: c tile already in smem (prefetched); hs overlays stages
    __syncthreads();   // all warps done with stage-region ldmatrix reads
    float* cs = (float*)(smraw + CS_OFF);                   // [128][36] f32
    __nv_bfloat16* hs = (__nv_bfloat16*)smraw;              // [128][36] bf16

    const bool evenT = ((t & 1) == 0);
    const bool useX = (Xaddb != nullptr);
    #pragma unroll
    for (int mi = 0; mi < 2; ++mi) {
        const int r0 = wm + mi * 16 + g;
        const int r1 = r0 + 8;
        const float it0 = intent ? intent[m0 + r0] : 0.f;
        const float it1 = intent ? intent[m0 + r1] : 0.f;
        #pragma unroll
        for (int ni = 0; ni < 4; ++ni) {
            const int lcol = wn + ni * 8 + t * 2;
            const int col  = n0 + lcol;
            const int hidl = lcol >> 2;
            float b0 = bias ? bias[col] : 0.f;
            float b1 = bias ? bias[col + 1] : 0.f;
            float v00 = acc[mi][ni][0] + b0;
            float v01 = acc[mi][ni][1] + b1;
            float v10 = acc[mi][ni][2] + b0;
            float v11 = acc[mi][ni][3] + b1;
            if (intent) {
                float w0 = wrow[col], w1 = wrow[col + 1];
                v00 = fmaf(it0, w0, v00); v01 = fmaf(it0, w1, v01);
                v10 = fmaf(it1, w0, v10); v11 = fmaf(it1, w1, v11);
            }
            if (useX) {
                float2 x0 = __bfloat1622float2(
                    *(const __nv_bfloat162*)(Xaddb + (size_t)(m0 + r0) * N4H + col));
                float2 x1 = __bfloat1622float2(
                    *(const __nv_bfloat162*)(Xaddb + (size_t)(m0 + r1) * N4H + col));
                v00 += x0.x; v01 += x0.y; v10 += x1.x; v11 += x1.y;
            }

            // even t: (i,f); odd t: (g,o)
            float a0, a1;
            if (evenT) { a0 = sig_fast(v00);  a1 = sig_fast(v10); }
            else       { a0 = tanh_fast(v00); a1 = tanh_fast(v10); }
            float bv0 = sig_fast(v01);
            float bv1 = sig_fast(v11);

            float pa0 = __shfl_xor_sync(0xffffffffu, a0, 1);
            float pa1 = __shfl_xor_sync(0xffffffffu, a1, 1);

            float tc0 = 0.f, tc1 = 0.f;
            if (evenT) {
                float cn0 = fmaf(bv0, cs[r0 * CS_LD + hidl], a0 * pa0);
                float cn1 = fmaf(bv1, cs[r1 * CS_LD + hidl], a1 * pa1);
                cs[r0 * CS_LD + hidl] = cn0;
                cs[r1 * CS_LD + hidl] = cn1;
                tc0 = tanh_fast(cn0);
                tc1 = tanh_fast(cn1);
            }
            float q0 = __shfl_xor_sync(0xffffffffu, tc0, 1);
            float q1 = __shfl_xor_sync(0xffffffffu, tc1, 1);
            if (!evenT) {
                hs[r0 * CS_LD + hidl] = __float2bfloat16(bv0 * q0);
                hs[r1 * CS_LD + hidl] = __float2bfloat16(bv1 * q1);
            }
        }
    }
    __syncthreads();

    // coalesced store of c and h tiles
    #pragma unroll 2
    for (int i = tid; i < BM * 32; i += 512) {
        int r = i >> 5, cc = i & 31;
        cell_c[(size_t)(m0 + r) * cc_ld + cc_off + hid0 + cc] = cs[r * CS_LD + cc];
        Hb[(size_t)(m0 + r) * hb_ld + hb_off + hid0 + cc]     = hs[r * CS_LD + cc];
    }
}

// ===========================================================================
// init GEMM (256 threads, plain epilogue): C = A@B + bias
// ===========================================================================
#define IBM 128
#define IBN 128
#define IBK 32

__global__ __launch_bounds__(256, 2)
void gemm_init(const __nv_bfloat16* __restrict__ A, int lda,
               const __nv_bfloat16* __restrict__ B, int ldb, int K,
               const float* __restrict__ bias,
               float* __restrict__ C,
               __nv_bfloat16* __restrict__ Cb, int ldc)
{
    __shared__ __nv_bfloat16 As[2][IBM * LDA_H];
    __shared__ __nv_bfloat16 Bs[2][IBK * LDB_H];

    const int tid  = threadIdx.x;
    const int lane = tid & 31;
    const int wid  = tid >> 5;
    const int wm   = (wid & 1) * 64;
    const int wn   = (wid >> 1) * 32;
    const int g    = lane >> 2;
    const int t    = lane & 3;
    const int m0   = blockIdx.y * IBM;
    const int n0   = blockIdx.x * IBN;

    const uint32_t as_base = smem_u32(&As[0][0]);
    const uint32_t bs_base = smem_u32(&Bs[0][0]);
    const uint32_t as_sz = IBM * LDA_H * 2;
    const uint32_t bs_sz = IBK * LDB_H * 2;

    float acc[4][4][4];
    #pragma unroll
    for (int mi = 0; mi < 4; ++mi)
        #pragma unroll
        for (int ni = 0; ni < 4; ++ni)
            #pragma unroll
            for (int r = 0; r < 4; ++r) acc[mi][ni][r] = 0.f;

    const int arow = tid >> 1;
    const int aoff = (tid & 1) * 16;
    const int brow = tid >> 4;
    const int boff = (tid & 15) * 8;
    const int ktotal = K / IBK;

    auto issue = [&](int kt, int b) {
        const __nv_bfloat16* asrc = A + (size_t)(m0 + arow) * lda + kt * IBK + aoff;
        uint32_t adst = as_base + b * as_sz + (arow * LDA_H + aoff) * 2;
        cp16(adst, asrc);
        cp16(adst + 16, asrc + 8);
        const __nv_bfloat16* bsrc = B + (size_t)(kt * IBK + brow) * ldb + n0 + boff;
        uint32_t bdst = bs_base + b * bs_sz + (brow * LDB_H + boff) * 2;
        cp16(bdst, bsrc);
        cp16(bdst + 16 * LDB_H * 2, bsrc + (size_t)16 * ldb);
    };

    issue(0, 0);
    CP_COMMIT();

    const int a_lrow = lane & 15;
    const int a_lcol = (lane >> 4) << 3;
    const int b_lrow = (lane & 7) + (lane & 8);
    const int b_lcol = (lane >> 4) << 3;

    #pragma unroll 1
    for (int kt = 0; kt < ktotal; ++kt) {
        if (kt + 1 < ktotal) {
            issue(kt + 1, (kt + 1) & 1);
            CP_COMMIT();
            cp_wait<1>();
        } else {
            cp_wait<0>();
        }
        __syncthreads();

        const int b = kt & 1;
        const uint32_t asb = as_base + b * as_sz;
        const uint32_t bsb = bs_base + b * bs_sz;

        #pragma unroll
        for (int kk = 0; kk < 2; ++kk) {
            const int kc = kk * 16;
            uint32_t afr[4][4];
            #pragma unroll
            for (int mi = 0; mi < 4; ++mi)
                ldm_x4(afr[mi], asb + ((wm + mi * 16 + a_lrow) * LDA_H + kc + a_lcol) * 2);
            uint32_t bfr[4][2];
            #pragma unroll
            for (int nj = 0; nj < 2; ++nj) {
                uint32_t r[4];
                ldm_x4t(r, bsb + ((kc + b_lrow) * LDB_H + wn + nj * 16 + b_lcol) * 2);
                bfr[nj*2+0][0] = r[0]; bfr[nj*2+0][1] = r[1];
                bfr[nj*2+1][0] = r[2]; bfr[nj*2+1][1] = r[3];
            }
            #pragma unroll
            for (int mi = 0; mi < 4; ++mi)
                #pragma unroll
                for (int ni = 0; ni < 4; ++ni)
                    mma_bf16(acc[mi][ni], afr[mi], bfr[ni][0], bfr[ni][1]);
        }
        __syncthreads();
    }

    #pragma unroll
    for (int mi = 0; mi < 4; ++mi) {
        const int row0 = m0 + wm + mi * 16 + g;
        const int row1 = row0 + 8;
        #pragma unroll
        for (int ni = 0; ni < 4; ++ni) {
            const int col = n0 + wn + ni * 8 + t * 2;
            float b0 = bias ? bias[col] : 0.f;
            float b1 = bias ? bias[col + 1] : 0.f;
            float v00 = acc[mi][ni][0] + b0;
            float v01 = acc[mi][ni][1] + b1;
            float v10 = acc[mi][ni][2] + b0;
            float v11 = acc[mi][ni][3] + b1;
            if (C) {
                *(float2*)(C + (size_t)row0 * ldc + col) = make_float2(v00, v01);
                *(float2*)(C + (size_t)row1 * ldc + col) = make_float2(v10, v11);
            }
            if (Cb) {
                *(__nv_bfloat162*)(Cb + (size_t)row0 * ldc + col) =
                    __nv_bfloat162(__float2bfloat16(v00), __float2bfloat16(v01));
                *(__nv_bfloat162*)(Cb + (size_t)row1 * ldc + col) =
                    __nv_bfloat162(__float2bfloat16(v10), __float2bfloat16(v11));
            }
        }
    }
}

// ===========================================================================
// setup kernels
// ===========================================================================
__global__ void cvt_all_kernel(const float* __restrict__ enc,
                               const float* __restrict__ ctx,
                               const float* __restrict__ Wh,
                               const float* __restrict__ Wc,
                               __nv_bfloat16* __restrict__ bEnc,
                               __nv_bfloat16* __restrict__ bCtx,
                               __nv_bfloat16* __restrict__ bWh,
                               __nv_bfloat16* __restrict__ bWc)
{
    const int n1 = BB * DD, n2 = DD * 2 * HH;
    int i = blockIdx.x * blockDim.x + threadIdx.x;
    int stride = gridDim.x * blockDim.x;
    int total = 2 * n1 + 2 * n2;
    for (; i < total; i += stride) {
        if (i < n1)               bEnc[i]              = __float2bfloat16(enc[i]);
        else if (i < 2 * n1)      bCtx[i - n1]         = __float2bfloat16(ctx[i - n1]);
        else if (i < 2 * n1 + n2) bWh[i - 2 * n1]      = __float2bfloat16(Wh[i - 2 * n1]);
        else                      bWc[i - 2 * n1 - n2] = __float2bfloat16(Wc[i - 2 * n1 - n2]);
    }
}

// gate-interleave permutation of K x 2048 weight matrices into bf16
__global__ void cvt_perm_kernel(const float* __restrict__ Whh0,
                                const float* __restrict__ Wih1,
                                const float* __restrict__ Whh1,
                                const float* __restrict__ Wih0,
                                __nv_bfloat16* __restrict__ bWhh0,
                                __nv_bfloat16* __restrict__ bW1s,
                                __nv_bfloat16* __restrict__ bWi0c)
{
    int i = blockIdx.x * blockDim.x + threadIdx.x;
    int stride = gridDim.x * blockDim.x;
    const int nA = HH * N4H;
    const int nB = HH * N4H;
    const int nC = HH * N4H;
    const int nD = DD * N4H;
    int total = nA + nB + nC + nD;
    for (; i < total; i += stride) {
        int j = i, k, c;
        const float* src;
        __nv_bfloat16* dst;
        if (j < nA)            { src = Whh0;  dst = bWhh0; }
        else if (j < nA + nB)  { j -= nA;  src = Wih1; dst = bW1s; }
        else if (j < nA+nB+nC) { j -= nA + nB; src = Whh1; dst = bW1s + (size_t)HH * N4H; }
        else                   { j -= nA + nB + nC; src = Wih0 + N4H; dst = bWi0c; }
        k = j >> 11;
        c = j & (N4H - 1);
        int o = ((c & 3) << 9) + (c >> 2);
        dst[j] = __float2bfloat16(src[(size_t)k * N4H + o]);
    }
}

__global__ void bias_prep_kernel(const float* __restrict__ b_ih0,
                                 const float* __restrict__ b_hh0,
                                 const float* __restrict__ b_ih1,
                                 const float* __restrict__ b_hh1,
                                 const float* __restrict__ wih0_row0,
                                 float* __restrict__ bsum0p,
                                 float* __restrict__ bsum1p,
                                 float* __restrict__ wrowp)
{
    int c = blockIdx.x * blockDim.x + threadIdx.x;
    if (c >= N4H) return;
    int o = ((c & 3) << 9) + (c >> 2);
    bsum0p[c] = b_ih0[o] + b_hh0[o];
    bsum1p[c] = b_ih1[o] + b_hh1[o];
    wrowp[c]  = wih0_row0[o];
}

// ===========================================================================
// head: out[b*stride] = sigmoid(relu(h1@W1+b1)@W2+b2); h1 bf16 strided.
// W1 ORIGINAL layout [512][32] (coalesced + broadcast); 4 acc chains.
// Fires PDL trigger at entry so the dependent gemm0 may begin its mainloop.
// ===========================================================================
__global__ void head_kernel(const __nv_bfloat16* __restrict__ H1, int hld,
                            const float* __restrict__ W1,
                            const float* __restrict__ b1,
                            const float* __restrict__ W2,
                            const float* __restrict__ b2,
                            float* __restrict__ out, int out_stride,
                            float* __restrict__ intent_next)
{
    cudaTriggerProgrammaticLaunchCompletion();

    int gwarp = (blockIdx.x * blockDim.x + threadIdx.x) >> 5;
    int lane  = threadIdx.x & 31;
    if (gwarp >= BB) return;
    const uint4* h4 = (const uint4*)(H1 + (size_t)gwarp * hld);    // 8 halfs
    float a0 = 0.f, a1 = 0.f, a2 = 0.f, a3 = 0.f;
    #pragma unroll 4
    for (int k8 = 0; k8 < HH / 8; ++k8) {
        uint4 hv = __ldg(h4 + k8);
        const float* wr = W1 + (k8 * 8) * 32 + lane;
        float2 f;
        f = __bfloat1622float2(*(__nv_bfloat162*)&hv.x);
        a0 = fmaf(f.x, __ldg(wr + 0 * 32), a0);
        a1 = fmaf(f.y, __ldg(wr + 1 * 32), a1);
        f = __bfloat1622float2(*(__nv_bfloat162*)&hv.y);
        a2 = fmaf(f.x, __ldg(wr + 2 * 32), a2);
        a3 = fmaf(f.y, __ldg(wr + 3 * 32), a3);
        f = __bfloat1622float2(*(__nv_bfloat162*)&hv.z);
        a0 = fmaf(f.x, __ldg(wr + 4 * 32), a0);
        a1 = fmaf(f.y, __ldg(wr + 5 * 32), a1);
        f = __bfloat1622float2(*(__nv_bfloat162*)&hv.w);
        a2 = fmaf(f.x, __ldg(wr + 6 * 32), a2);
        a3 = fmaf(f.y, __ldg(wr + 7 * 32), a3);
    }
    float acc = ((a0 + a1) + (a2 + a3)) + b1[lane];
    acc = fmaxf(acc, 0.f);
    float v = acc * W2[lane];
    #pragma unroll
    for (int off = 16; off; off >>= 1)
        v += __shfl_xor_sync(0xffffffffu, v, off);
    if (lane == 0) {
        float logit = v + b2[0];
        float it = 1.f / (1.f + expf(-logit));
        out[(size_t)gwarp * out_stride] = it;
        if (intent_next) intent_next[gwarp] = it;
    }
}

// ===========================================================================
extern "C" void kernel_launch(void* const* d_in, const int* in_sizes, int n_in,
                              void* d_out, int out_size)
{
    const float* encoder = (const float*)d_in[0];
    const float* context = (const float*)d_in[1];
    const float* init_it = (const float*)d_in[2];
    const float* Wh_init = (const float*)d_in[3];
    const float* bh_init = (const float*)d_in[4];
    const float* Wc_init = (const float*)d_in[5];
    const float* bc_init = (const float*)d_in[6];
    const float* W_ih0   = (const float*)d_in[7];
    const float* W_hh0   = (const float*)d_in[8];
    const float* b_ih0   = (const float*)d_in[9];
    const float* b_hh0   = (const float*)d_in[10];
    const float* W_ih1   = (const float*)d_in[11];
    const float* W_hh1   = (const float*)d_in[12];
    const float* b_ih1   = (const float*)d_in[13];
    const float* b_hh1   = (const float*)d_in[14];
    const float* Wo1     = (const float*)d_in[15];
    const float* bo1     = (const float*)d_in[16];
    const float* Wo2     = (const float*)d_in[17];
    const float* bo2     = (const float*)d_in[18];
    const float* Wg1     = (const float*)d_in[19];
    const float* bg1     = (const float*)d_in[20];
    const float* Wg2     = (const float*)d_in[21];
    const float* bg2     = (const float*)d_in[22];
    float* out = (float*)d_out;

    float *C01, *intent, *bsum0p, *bsum1p, *wrowp;
    cudaGetSymbolAddress((void**)&C01, g_C01);
    cudaGetSymbolAddress((void**)&intent, g_intent);
    cudaGetSymbolAddress((void**)&bsum0p, g_bsum0p);
    cudaGetSymbolAddress((void**)&bsum1p, g_bsum1p);
    cudaGetSymbolAddress((void**)&wrowp,  g_wrowp);

    __nv_bfloat16 *Xcb, *bH01, *bEnc, *bCtx, *bWh, *bWc, *bWi0c, *bWhh0, *bW1s;
    cudaGetSymbolAddress((void**)&Xcb,  g_Xcb);
    cudaGetSymbolAddress((void**)&bH01, g_bH01);
    cudaGetSymbolAddress((void**)&bEnc, g_bEnc);
    cudaGetSymbolAddress((void**)&bCtx, g_bCtx);
    cudaGetSymbolAddress((void**)&bWh,  g_bWh);
    cudaGetSymbolAddress((void**)&bWc,  g_bWc);
    cudaGetSymbolAddress((void**)&bWi0c, g_bWi0c);
    cudaGetSymbolAddress((void**)&bWhh0, g_bWhh0);
    cudaGetSymbolAddress((void**)&bW1s,  g_bW1s);

    cudaFuncSetAttribute(gemm_step, cudaFuncAttributeMaxDynamicSharedMemorySize,
                         DYN_SMEM);

    // ---- setup ----
    cvt_all_kernel<<<1024, 256>>>(encoder, context, Wh_init, Wc_init,
                                  bEnc, bCtx, bWh, bWc);
    cvt_perm_kernel<<<2048, 256>>>(W_hh0, W_ih1, W_hh1, W_ih0,
                                   bWhh0, bW1s, bWi0c);
    bias_prep_kernel<<<8, 256>>>(b_ih0, b_hh0, b_ih1, b_hh1, W_ih0,
                                 bsum0p, bsum1p, wrowp);

    // ---- init: [h0|h1] = enc@Wh + bh ; [c0|c1] = enc@Wc + bc (stacked) ----
    dim3 gridInit(2 * HH / IBN, BB / IBM);   // (8, 32)
    gemm_init<<<gridInit, 256>>>(bEnc, DD, bWh, 2 * HH, DD, bh_init,
                                 nullptr, bH01, 2 * HH);
    gemm_init<<<gridInit, 256>>>(bEnc, DD, bWc, 2 * HH, DD, bc_init,
                                 C01, nullptr, 2 * HH);

    // ---- Xc (bf16) = ctx @ bWi0c + bsum0p (normal launch) ----
    dim3 gridStep(N4H / BN, BB / BM);        // (16, 32)
    gemm_step<<<gridStep, 512, DYN_SMEM>>>(bCtx, DD, bWi0c, N4H, DD,
                                           bsum0p, nullptr, nullptr, nullptr,
                                           Xcb, N4H,
                                           nullptr, 0, 0, nullptr, 0, 0);

    // PDL launch config for gemm0 (overlaps with preceding head kernel)
    cudaLaunchAttribute pdl_attr;
    pdl_attr.id = cudaLaunchAttributeProgrammaticStreamSerialization;
    pdl_attr.val.programmaticStreamSerializationAllowed = 1;
    cudaLaunchConfig_t cfg = {};
    cfg.gridDim = gridStep;
    cfg.blockDim = dim3(512);
    cfg.dynamicSmemBytes = DYN_SMEM;
    cfg.stream = 0;
    cfg.attrs = &pdl_attr;
    cfg.numAttrs = 1;

    // ---- time loop: 3 launches per step ----
    for (int t = 0; t < TT; ++t) {
        const float* it = (t == 0) ? init_it : intent;

        // layer0 (PDL): gates = h0 @ bWhh0 + Xcb + intent*wrow -> fused cell
        cudaLaunchKernelEx(&cfg, gemm_step,
                           (const __nv_bfloat16*)bH01, (int)(2 * HH),
                           (const __nv_bfloat16*)bWhh0, (int)N4H, (int)HH,
                           (const float*)nullptr,
                           (const __nv_bfloat16*)Xcb,
                           it,
                           (const float*)wrowp,
                           (__nv_bfloat16*)nullptr, 0,
                           C01, (int)(2 * HH), 0,
                           bH01, (int)(2 * HH), 0);

        // layer1 (normal): gates = [h0n|h1] @ bW1s + bsum1p -> fused cell
        gemm_step<<<gridStep, 512, DYN_SMEM>>>(bH01, 2 * HH, bW1s, N4H, 2 * HH,
                                               bsum1p, nullptr, nullptr, nullptr,
                                               nullptr, 0,
                                               C01, 2 * HH, HH,
                                               bH01, 2 * HH, HH);

        head_kernel<<<BB / 8, 256>>>(bH01 + HH, 2 * HH, Wo1, bo1, Wo2, bo2,
                                     out + t, TT, intent);
    }

    head_kernel<<<BB / 8, 256>>>(bH01 + HH, 2 * HH, Wg1, bg1, Wg2, bg2,
                                 out + (size_t)BB * TT, 1, nullptr);
}